// round 11
// baseline (speedup 1.0000x reference)
#include <cuda_runtime.h>
#include <cuda_bf16.h>
#include <mma.h>
#include <cstdint>
using namespace nvcuda;

#define NN 512
#define RST 516
#define NWARP 16
#define WLAST (NWARP - 1)

// ---------------- device scratch (no allocations allowed) ----------------
__device__ __align__(16) float2 g_slot[2 * 512 * 512];   // 4 MB
__device__ float g_U [NN * NN];
__device__ float g_Vs[NN * NN];
__device__ __align__(16) __nv_bfloat16 g_xhi[32768 * 512];   // 32 MB
__device__ __align__(16) __nv_bfloat16 g_xlo[32768 * 512];   // 32 MB
__device__ __align__(16) __nv_bfloat16 g_whi[NN * NN];
__device__ __align__(16) __nv_bfloat16 g_wlo[NN * NN];

__device__ __forceinline__ uint32_t smem_u32(const void* p) {
    uint32_t a;
    asm("{ .reg .u64 t; cvta.to.shared.u64 t, %1; cvt.u32.u64 %0, t; }" : "=r"(a) : "l"(p));
    return a;
}
#define CP_ASYNC16(sa, gp) \
    asm volatile("cp.async.ca.shared.global [%0], [%1], 16;" :: "r"(sa), "l"(gp) : "memory")
#define CP_COMMIT() asm volatile("cp.async.commit_group;" ::: "memory")
#define CP_WAIT(n)  asm volatile("cp.async.wait_group %0;" :: "n"(n) : "memory")

// ---------------- 1) cos/sin precompute into padded slots ----------------
__global__ void setup_cs_kernel(const float* __restrict__ phiU,
                                const float* __restrict__ phiV) {
    int tid = blockIdx.x * blockDim.x + threadIdx.x;
    if (tid >= 2 * 512 * 512) return;
    int mat = tid >> 18;
    int r   = tid & 262143;
    int i   = r >> 9;
    int m   = r & 511;
    float c = 1.0f, s = 0.0f;
    if (m < 511 - i) {
        int k = i * 511 - (i * (i - 1)) / 2 + m;
        float ph = mat ? __ldg(&phiV[k]) : __ldg(&phiU[k]);
        sincosf(ph, &s, &c);
    }
    g_slot[tid] = make_float2(c, s);
}

// ---------------- 1b) split x into bf16 hi/lo (one pass) ----------------
__global__ void xsplit_kernel(const float* __restrict__ x) {
    int i = (blockIdx.x * 256 + threadIdx.x) * 8;
    float4 v0 = *(const float4*)(x + i);
    float4 v1 = *(const float4*)(x + i + 4);
    __nv_bfloat16 h[8], l[8];
    const float* vv = (const float*)&v0;
    #pragma unroll
    for (int e = 0; e < 8; e++) {
        float f = (e < 4) ? vv[e] : ((const float*)&v1)[e - 4];
        h[e] = __float2bfloat16_rn(f);
        l[e] = __float2bfloat16_rn(f - __bfloat162float(h[e]));
    }
    *(uint4*)(g_xhi + i) = *(uint4*)h;
    *(uint4*)(g_xlo + i) = *(uint4*)l;
}

// ---------------- 2) Givens-mesh reconstruction, 1-barrier pivots, 16 warps ----------------
// Same verified algorithm as round 10, W parameterized 8 -> 16: per-warp slice
// Lc halves so both serial chains (phase1 D-chain, phase2 A-chain) halve.
#define P2STEP(u, cc, ss) do { float _t2 = (cc)*(u); float _t1 = (ss)*(u); \
                               (u) = fmaf((ss), A, _t2); A = fmaf((cc), A, -_t1); } while (0)
#define P1STEP(u, cc, ss) do { Dw = fmaf((cc), Dw, (ss)*(u)); Cw = (cc)*Cw; } while (0)

__global__ void __launch_bounds__(512) reconstruct_kernel(const float* __restrict__ dU,
                                                          const float* __restrict__ dV,
                                                          const float* __restrict__ sigma) {
    extern __shared__ float sm[];
    float*  cols  = sm;                               // 32*RST floats
    float2* ring0 = (float2*)(sm + 32 * RST);         // 2 x 512 float2
    float*  Csh   = (float*)(ring0 + 1024);           // 2 x 16
    float*  Dsh   = Csh + 32;                         // 2 x 16 x 32
    float*  A0sh  = Dsh + 1024;                       // 2 x 32

    const int mat     = blockIdx.x >> 4;
    const int colbase = (blockIdx.x & 15) << 5;
    const int tid  = threadIdx.x;
    const int w    = tid >> 5;
    const int lane = tid & 31;
    const int col  = colbase + lane;

    const float4* slotf4 = (const float4*)(g_slot + mat * 262144);  // 256 f4/pivot
    float* myc = cols + lane * RST;

    // identity columns: warp w fills rows [w*32, w*32+32)
    for (int r = w * 32; r < w * 32 + 32; r += 4) {
        float4 z = make_float4(0.f, 0.f, 0.f, 0.f);
        if (col >= r && col < r + 4) ((float*)&z)[col - r] = 1.0f;
        *(float4*)&myc[r] = z;
    }

    for (int B = 0; B < 511; B += 64) {
        const int Bend = (B + 64 < 511) ? B + 64 : 511;
        const int LB = 511 - B;
        const int Lc = ((LB + 127) >> 7) << 3;       // per-warp chunk, mult of 8
        const int m0 = w * Lc;
        const int f40 = m0 >> 1;                     // slice start in float4
        const int nf4 = (w == WLAST) ? 32 : (Lc >> 1);
        const bool lact = (lane < nf4) && (f40 + lane < 256);

        __syncthreads();                             // block barrier

        // stage A0 for the first pivot of the block
        if (w == WLAST) A0sh[(B & 1) * 32 + lane] = myc[B];

        // prime cs: stage slice(B), prefetch slice(B+1), issue slice(B+2)
        float4 pf, pf2;
        {
            float4* rw = (float4*)(ring0 + (B & 1) * 512);
            if (lact) {
                float4 s0 = __ldg(slotf4 + B * 256 + f40 + lane);
                rw[f40 + lane] = s0;
                int i1 = (B + 1 <= 510) ? B + 1 : 510;
                int i2 = (B + 2 <= 510) ? B + 2 : 510;
                pf  = __ldg(slotf4 + i1 * 256 + f40 + lane);
                pf2 = __ldg(slotf4 + i2 * 256 + f40 + lane);
            }
            __syncwarp();
        }

        for (int i = B; i < Bend; i++) {
            const int par = i & 1;
            const int L = 511 - i;
            const int mm0 = (m0 < L) ? m0 : L;
            const int m1  = (w == WLAST) ? L : ((m0 + Lc < L) ? m0 + Lc : L);

            const float2* ringp = ring0 + par * 512;
            const float4* rf    = (const float4*)ringp;

            // stage A0 for THIS pivot (owner warp; i==B handled at prime)
            if (i > B) {
                int wown = L / Lc; if (wown > WLAST) wown = WLAST;
                if (w == wown) A0sh[par * 32 + lane] = myc[i];
            }

            float Cw = 1.0f, Dw = 0.0f;

            // ---- phase 1: (C, D) over own slice ----
            {
                int nfull = (m1 - mm0) >> 3;
                int m = mm0;
                if (nfull > 0) {
                    int j = 511 - m;
                    float4 va = *(float4*)&myc[j - 3];
                    float4 vb = *(float4*)&myc[j - 7];
                    float4 r0 = rf[(m >> 1) + 0], r1 = rf[(m >> 1) + 1];
                    float4 r2 = rf[(m >> 1) + 2], r3 = rf[(m >> 1) + 3];
                    for (int g = 0; g < nfull; g++) {
                        float4 nva = va, nvb = vb, n0 = r0, n1 = r1, n2 = r2, n3 = r3;
                        if (g + 1 < nfull) {
                            int mn = m + 8, jn = 511 - mn;
                            n0 = rf[(mn >> 1) + 0]; n1 = rf[(mn >> 1) + 1];
                            n2 = rf[(mn >> 1) + 2]; n3 = rf[(mn >> 1) + 3];
                            nva = *(float4*)&myc[jn - 3];
                            nvb = *(float4*)&myc[jn - 7];
                        }
                        P1STEP(va.w, r0.x, r0.y);  P1STEP(va.z, r0.z, r0.w);
                        P1STEP(va.y, r1.x, r1.y);  P1STEP(va.x, r1.z, r1.w);
                        P1STEP(vb.w, r2.x, r2.y);  P1STEP(vb.z, r2.z, r2.w);
                        P1STEP(vb.y, r3.x, r3.y);  P1STEP(vb.x, r3.z, r3.w);
                        va = nva; vb = nvb; r0 = n0; r1 = n1; r2 = n2; r3 = n3;
                        m += 8;
                    }
                }
                for (; m < m1; m++) {
                    float2 p = ringp[m];
                    float  u = myc[511 - m];
                    Dw = fmaf(p.x, Dw, p.y * u);
                    Cw = p.x * Cw;
                }
            }

            if (lane == 0) Csh[par * 16 + w] = Cw;
            Dsh[par * 512 + w * 32 + lane] = Dw;

            // stage next pivot's cs slice; refill pf2 from slice(i+3)
            if (i + 1 < Bend) {
                __syncwarp();          // own phase2(i-1) reads of parity^1 done
                float4* rw = (float4*)(ring0 + (par ^ 1) * 512);
                if (lact) {
                    rw[f40 + lane] = pf;
                    pf = pf2;
                    int nx = (i + 3 <= 510) ? i + 3 : 510;
                    pf2 = __ldg(slotf4 + nx * 256 + f40 + lane);
                }
            }

            __syncthreads();           // the one barrier: stitch

            // fold incoming A
            float A = A0sh[par * 32 + lane];
            #pragma unroll 15
            for (int kk = 0; kk < w; kk++)
                A = fmaf(Csh[par * 16 + kk], A, -Dsh[par * 512 + kk * 32 + lane]);
            if (w == WLAST) myc[i] = fmaf(Cw, A, -Dw);   // final pivot value

            // ---- phase 2: replay own slice ----
            {
                int nfull = (m1 - mm0) >> 3;
                int m = mm0;
                if (nfull > 0) {
                    int j = 511 - m;
                    float4 va = *(float4*)&myc[j - 3];
                    float4 vb = *(float4*)&myc[j - 7];
                    float4 r0 = rf[(m >> 1) + 0], r1 = rf[(m >> 1) + 1];
                    float4 r2 = rf[(m >> 1) + 2], r3 = rf[(m >> 1) + 3];
                    for (int g = 0; g < nfull; g++) {
                        float4 nva = va, nvb = vb, n0 = r0, n1 = r1, n2 = r2, n3 = r3;
                        if (g + 1 < nfull) {
                            int mn = m + 8, jn = 511 - mn;
                            n0 = rf[(mn >> 1) + 0]; n1 = rf[(mn >> 1) + 1];
                            n2 = rf[(mn >> 1) + 2]; n3 = rf[(mn >> 1) + 3];
                            nva = *(float4*)&myc[jn - 3];
                            nvb = *(float4*)&myc[jn - 7];
                        }
                        P2STEP(va.w, r0.x, r0.y);  P2STEP(va.z, r0.z, r0.w);
                        P2STEP(va.y, r1.x, r1.y);  P2STEP(va.x, r1.z, r1.w);
                        P2STEP(vb.w, r2.x, r2.y);  P2STEP(vb.z, r2.z, r2.w);
                        P2STEP(vb.y, r3.x, r3.y);  P2STEP(vb.x, r3.z, r3.w);
                        int jj = 511 - m;
                        *(float4*)&myc[jj - 3] = va;
                        *(float4*)&myc[jj - 7] = vb;
                        va = nva; vb = nvb; r0 = n0; r1 = n1; r2 = n2; r3 = n3;
                        m += 8;
                    }
                }
                for (; m < m1; m++) {
                    float2 p = ringp[m];
                    int jj = 511 - m;
                    float u = myc[jj];
                    float t2 = p.x * u, t1 = p.y * u;
                    myc[jj] = fmaf(p.y, A, t2);
                    A = fmaf(p.x, A, -t1);
                }
            }
        }
    }
    __syncthreads();

    // writeback: warp w rows [w*32, w*32+32), coalesced across lanes
    if (mat == 0) {
        for (int r = w * 32; r < w * 32 + 32; r++)
            g_U[r * NN + col] = __ldg(&dU[r]) * myc[r];
    } else {
        for (int r = w * 32; r < w * 32 + 32; r++)
            g_Vs[r * NN + col] = __ldg(&sigma[r]) * __ldg(&dV[r]) * myc[r];
    }
}

// ---------------- 3) W = U @ (sigma*delta_V * V), bf16 hi/lo output ----------------
__global__ void wgemm_kernel() {
    __shared__ float As[32][33];
    __shared__ float Bs[32][33];
    const int tx = threadIdx.x, ty = threadIdx.y;
    const int a = blockIdx.y * 32 + ty;
    const int b = blockIdx.x * 32 + tx;
    float acc = 0.0f;
    for (int kt = 0; kt < NN; kt += 32) {
        As[ty][tx] = g_U [a * NN + kt + tx];
        Bs[ty][tx] = g_Vs[(kt + ty) * NN + b];
        __syncthreads();
        #pragma unroll
        for (int kk = 0; kk < 32; kk++)
            acc += As[ty][kk] * Bs[kk][tx];
        __syncthreads();
    }
    __nv_bfloat16 hi = __float2bfloat16_rn(acc);
    g_whi[a * NN + b] = hi;
    g_wlo[a * NN + b] = __float2bfloat16_rn(acc - __bfloat162float(hi));
}

// ---------------- 4) out = x @ W^T, 3-term bf16 wmma, cp.async pipeline ----------------
#define GBK 32
#define XLD 40
#define TILE_H (128 * XLD)
#define STAGE_H (4 * TILE_H)

__global__ void __launch_bounds__(256, 2) bfgemm_kernel(float* __restrict__ C) {
    __shared__ __nv_bfloat16 sbuf[2 * STAGE_H];

    const int tid  = threadIdx.x;
    const int warp = tid >> 5;
    const int m0 = blockIdx.y * 128;
    const int n0 = blockIdx.x * 128;
    const int wm = (warp >> 2) * 64;
    const int wn = (warp & 3) * 32;

    wmma::fragment<wmma::accumulator, 16, 16, 16, float> acc[4][2];
    #pragma unroll
    for (int i = 0; i < 4; i++)
        #pragma unroll
        for (int j = 0; j < 2; j++) wmma::fill_fragment(acc[i][j], 0.0f);

    const int lr = tid >> 1;
    const int lh = (tid & 1) * 16;
    const __nv_bfloat16* gx[4];
    gx[0] = g_xhi + (size_t)(m0 + lr) * NN + lh;
    gx[1] = g_xlo + (size_t)(m0 + lr) * NN + lh;
    gx[2] = g_whi + (size_t)(n0 + lr) * NN + lh;
    gx[3] = g_wlo + (size_t)(n0 + lr) * NN + lh;
    const uint32_t sb0 = smem_u32(sbuf);
    const uint32_t dst_row = (uint32_t)(lr * XLD + lh) * 2;

    #define COPY_TILE(t, stg) do { \
        uint32_t _b = sb0 + (stg) * (STAGE_H * 2); \
        int _k = (t) * GBK; \
        _Pragma("unroll") \
        for (int _p = 0; _p < 4; _p++) { \
            uint32_t _d = _b + _p * (TILE_H * 2) + dst_row; \
            CP_ASYNC16(_d,      gx[_p] + _k); \
            CP_ASYNC16(_d + 16, gx[_p] + _k + 8); \
        } } while (0)

    COPY_TILE(0, 0);
    CP_COMMIT();

    for (int t = 0; t < NN / GBK; t++) {
        const int cur = t & 1;
        if (t + 1 < NN / GBK) { COPY_TILE(t + 1, cur ^ 1); CP_COMMIT(); CP_WAIT(1); }
        else                  { CP_WAIT(0); }
        __syncthreads();

        const __nv_bfloat16* xh = sbuf + cur * STAGE_H;
        const __nv_bfloat16* xl = xh + TILE_H;
        const __nv_bfloat16* wh = xl + TILE_H;
        const __nv_bfloat16* wl = wh + TILE_H;

        #pragma unroll
        for (int ks = 0; ks < GBK; ks += 16) {
            wmma::fragment<wmma::matrix_a, 16, 16, 16, __nv_bfloat16, wmma::row_major> ah[4], al[4];
            wmma::fragment<wmma::matrix_b, 16, 16, 16, __nv_bfloat16, wmma::col_major> bh[2], bl[2];
            #pragma unroll
            for (int i = 0; i < 4; i++) {
                wmma::load_matrix_sync(ah[i], xh + (wm + i * 16) * XLD + ks, XLD);
                wmma::load_matrix_sync(al[i], xl + (wm + i * 16) * XLD + ks, XLD);
            }
            #pragma unroll
            for (int j = 0; j < 2; j++) {
                wmma::load_matrix_sync(bh[j], wh + (wn + j * 16) * XLD + ks, XLD);
                wmma::load_matrix_sync(bl[j], wl + (wn + j * 16) * XLD + ks, XLD);
            }
            #pragma unroll
            for (int i = 0; i < 4; i++)
                #pragma unroll
                for (int j = 0; j < 2; j++) {
                    wmma::mma_sync(acc[i][j], ah[i], bh[j], acc[i][j]);
                    wmma::mma_sync(acc[i][j], ah[i], bl[j], acc[i][j]);
                    wmma::mma_sync(acc[i][j], al[i], bh[j], acc[i][j]);
                }
        }
        __syncthreads();
    }

    #pragma unroll
    for (int i = 0; i < 4; i++)
        #pragma unroll
        for (int j = 0; j < 2; j++)
            wmma::store_matrix_sync(&C[(size_t)(m0 + wm + i * 16) * NN + n0 + wn + j * 16],
                                    acc[i][j], NN, wmma::mem_row_major);
}

// ---------------- launch ----------------
extern "C" void kernel_launch(void* const* d_in, const int* in_sizes, int n_in,
                              void* d_out, int out_size) {
    const float* x     = (const float*)d_in[0];
    const float* phiU  = (const float*)d_in[1];
    const float* dU    = (const float*)d_in[2];
    const float* phiV  = (const float*)d_in[3];
    const float* dV    = (const float*)d_in[4];
    const float* sigma = (const float*)d_in[5];
    float* out = (float*)d_out;

    const int recon_smem = 32 * RST * 4 + 1024 * 8 + (32 + 1024 + 64) * 4;
    cudaFuncSetAttribute(reconstruct_kernel,
                         cudaFuncAttributeMaxDynamicSharedMemorySize, recon_smem);

    setup_cs_kernel<<<(2 * 512 * 512 + 255) / 256, 256>>>(phiU, phiV);
    xsplit_kernel<<<32768 * 512 / (256 * 8), 256>>>(x);
    reconstruct_kernel<<<32, 512, recon_smem>>>(dU, dV, sigma);
    wgemm_kernel<<<dim3(16, 16), dim3(32, 32)>>>();
    bfgemm_kernel<<<dim3(NN / 128, 32768 / 128), 256>>>(out);
}

// round 12
// speedup vs baseline: 1.3737x; 1.3737x over previous
#include <cuda_runtime.h>
#include <cuda_bf16.h>
#include <mma.h>
#include <cstdint>
using namespace nvcuda;

#define NN 512
#define RST 516

// ---------------- device scratch (no allocations allowed) ----------------
__device__ __align__(16) float2 g_slot[2 * 512 * 512];   // 4 MB
__device__ float g_U [NN * NN];
__device__ float g_Vs[NN * NN];
__device__ __align__(16) __nv_bfloat16 g_xhi[32768 * 512];   // 32 MB
__device__ __align__(16) __nv_bfloat16 g_xlo[32768 * 512];   // 32 MB
__device__ __align__(16) __nv_bfloat16 g_whi[NN * NN];
__device__ __align__(16) __nv_bfloat16 g_wlo[NN * NN];

__device__ __forceinline__ uint32_t smem_u32(const void* p) {
    uint32_t a;
    asm("{ .reg .u64 t; cvta.to.shared.u64 t, %1; cvt.u32.u64 %0, t; }" : "=r"(a) : "l"(p));
    return a;
}
#define CP_ASYNC16(sa, gp) \
    asm volatile("cp.async.ca.shared.global [%0], [%1], 16;" :: "r"(sa), "l"(gp) : "memory")
#define CP_COMMIT() asm volatile("cp.async.commit_group;" ::: "memory")
#define CP_WAIT(n)  asm volatile("cp.async.wait_group %0;" :: "n"(n) : "memory")

// ---------------- 1) cos/sin precompute into padded slots ----------------
__global__ void setup_cs_kernel(const float* __restrict__ phiU,
                                const float* __restrict__ phiV) {
    int tid = blockIdx.x * blockDim.x + threadIdx.x;
    if (tid >= 2 * 512 * 512) return;
    int mat = tid >> 18;
    int r   = tid & 262143;
    int i   = r >> 9;
    int m   = r & 511;
    float c = 1.0f, s = 0.0f;
    if (m < 511 - i) {
        int k = i * 511 - (i * (i - 1)) / 2 + m;
        float ph = mat ? __ldg(&phiV[k]) : __ldg(&phiU[k]);
        sincosf(ph, &s, &c);
    }
    g_slot[tid] = make_float2(c, s);
}

// ---------------- 1b) split x into bf16 hi/lo (one pass) ----------------
__global__ void xsplit_kernel(const float* __restrict__ x) {
    int i = (blockIdx.x * 256 + threadIdx.x) * 8;
    float4 v0 = *(const float4*)(x + i);
    float4 v1 = *(const float4*)(x + i + 4);
    __nv_bfloat16 h[8], l[8];
    const float* vv = (const float*)&v0;
    #pragma unroll
    for (int e = 0; e < 8; e++) {
        float f = (e < 4) ? vv[e] : ((const float*)&v1)[e - 4];
        h[e] = __float2bfloat16_rn(f);
        l[e] = __float2bfloat16_rn(f - __bfloat162float(h[e]));
    }
    *(uint4*)(g_xhi + i) = *(uint4*)h;
    *(uint4*)(g_xlo + i) = *(uint4*)l;
}

// ---------------- 2) Givens-mesh reconstruction ----------------
// W=8 warps; lane owns a column. Per 64-pivot block, warp w owns the FIXED
// rotation range m in [w*LC, (w+1)*LC); rows j=511-m live in REGISTERS.
// Steps with m >= L use the slot padding (c=1,s=0) = exact identity, so
// loops are fully unrolled with no tails. Phase1/phase2 chains are split
// 2-way via half-slice (C,D) partials. One __syncthreads per pivot (stitch).
// Folds write myc[i] (authoritative for frozen rows); block-end writeback
// stores only still-active rows (m <= 511-Bend, which includes the next
// block's first pivot row, and uniformly row 511 at the very end).
template<int LC>
__device__ __forceinline__ void do_block(
    int B, int Bend, int w, int lane,
    float* __restrict__ myc, float2* __restrict__ ring0,
    float* __restrict__ Csh, float* __restrict__ Dsh, float* __restrict__ A0sh,
    const float4* __restrict__ slotf4)
{
    const int m0  = w * LC;
    const int f40 = m0 >> 1;
    const bool lact = lane < (LC / 2);
    const int fidx = f40 + lane;

    // load rows j = 511-(m0+k) into registers
    float v[LC];
    #pragma unroll
    for (int k = 0; k < LC; k++) v[k] = myc[511 - m0 - k];

    // prime ring: stage slice(B); prefetch slices B+1, B+2
    float4 pf, pf2;
    {
        float4* rw = (float4*)(ring0 + (B & 1) * 512);
        if (lact) {
            rw[fidx] = __ldg(slotf4 + B * 256 + fidx);
            int i1 = (B + 1 <= 510) ? B + 1 : 510;
            int i2 = (B + 2 <= 510) ? B + 2 : 510;
            pf  = __ldg(slotf4 + i1 * 256 + fidx);
            pf2 = __ldg(slotf4 + i2 * 256 + fidx);
        }
        __syncwarp();
    }

    for (int i = B; i < Bend; i++) {
        const int par = i & 1;
        const int L = 511 - i;
        const float4* rf = (const float4*)(ring0 + par * 512) + f40;

        if (i == B && w == 7) A0sh[par * 32 + lane] = myc[B];

        // ---- phase 1: two half-chains (C0,D0),(C1,D1) ----
        float C0 = 1.f, D0 = 0.f, C1 = 1.f, D1 = 0.f;
        #pragma unroll
        for (int q = 0; q < LC / 4; q++) {
            float4 r = rf[q];
            D0 = fmaf(r.x, D0, r.y * v[2 * q]);     C0 *= r.x;
            D0 = fmaf(r.z, D0, r.w * v[2 * q + 1]); C0 *= r.z;
        }
        #pragma unroll
        for (int q = LC / 4; q < LC / 2; q++) {
            float4 r = rf[q];
            D1 = fmaf(r.x, D1, r.y * v[2 * q]);     C1 *= r.x;
            D1 = fmaf(r.z, D1, r.w * v[2 * q + 1]); C1 *= r.z;
        }
        const float Cw = C0 * C1;
        const float Dw = fmaf(C1, D0, D1);

        if (lane == 0) Csh[par * 8 + w] = Cw;
        Dsh[par * 256 + w * 32 + lane] = Dw;

        // stage ring for pivot i+1; refill pf2 from slice(i+3)
        if (i + 1 < Bend) {
            __syncwarp();
            float4* rw = (float4*)(ring0 + (par ^ 1) * 512);
            if (lact) {
                rw[fidx] = pf;
                pf = pf2;
                int nx = (i + 3 <= 510) ? i + 3 : 510;
                pf2 = __ldg(slotf4 + nx * 256 + fidx);
            }
        }

        __syncthreads();                           // the one barrier: stitch

        float A = A0sh[par * 32 + lane];
        #pragma unroll 7
        for (int kk = 0; kk < w; kk++)
            A = fmaf(Csh[par * 8 + kk], A, -Dsh[par * 256 + kk * 32 + lane]);
        if (w == 7) myc[i] = fmaf(Cw, A, -Dw);     // final pivot value

        // ---- phase 2: two half-chains; 2nd half seeds from A1 = C0*A - D0 ----
        float A1 = fmaf(C0, A, -D0);
        #pragma unroll
        for (int q = 0; q < LC / 4; q++) {
            float4 r = rf[q];
            { float u = v[2 * q];     float t1 = r.y * u;
              v[2 * q]     = fmaf(r.y, A, r.x * u); A = fmaf(r.x, A, -t1); }
            { float u = v[2 * q + 1]; float t1 = r.w * u;
              v[2 * q + 1] = fmaf(r.w, A, r.z * u); A = fmaf(r.z, A, -t1); }
        }
        #pragma unroll
        for (int q = LC / 4; q < LC / 2; q++) {
            float4 r = rf[q];
            { float u = v[2 * q];     float t1 = r.y * u;
              v[2 * q]     = fmaf(r.y, A1, r.x * u); A1 = fmaf(r.x, A1, -t1); }
            { float u = v[2 * q + 1]; float t1 = r.w * u;
              v[2 * q + 1] = fmaf(r.w, A1, r.z * u); A1 = fmaf(r.z, A1, -t1); }
        }

        // extract next pivot's A0 (row i+1 <-> m = L-1) from owner's registers
        if (i + 1 < Bend) {
            int idx = (L - 1) - m0;
            if (idx >= 0 && idx < LC) {
                float val = 0.f;
                #pragma unroll
                for (int k = 0; k < LC; k++) if (k == idx) val = v[k];
                A0sh[((i + 1) & 1) * 32 + lane] = val;
            }
        }
    }

    // block-end writeback of still-active rows (m0+k <= 511-Bend)
    #pragma unroll
    for (int k = 0; k < LC; k++)
        if (m0 + k <= 511 - Bend) myc[511 - m0 - k] = v[k];
}

__global__ void __launch_bounds__(256) reconstruct_kernel(const float* __restrict__ dU,
                                                          const float* __restrict__ dV,
                                                          const float* __restrict__ sigma) {
    extern __shared__ float sm[];
    float*  cols  = sm;                               // 32*RST floats
    float2* ring0 = (float2*)(sm + 32 * RST);         // 2 x 512 float2
    float*  Csh   = (float*)(ring0 + 1024);           // 2 x 8
    float*  Dsh   = Csh + 16;                         // 2 x 8 x 32
    float*  A0sh  = Dsh + 512;                        // 2 x 32

    const int mat     = blockIdx.x >> 4;
    const int colbase = (blockIdx.x & 15) << 5;
    const int tid  = threadIdx.x;
    const int w    = tid >> 5;
    const int lane = tid & 31;
    const int col  = colbase + lane;

    const float4* slotf4 = (const float4*)(g_slot + mat * 262144);
    float* myc = cols + lane * RST;

    // identity columns
    for (int r = w * 64; r < w * 64 + 64; r += 4) {
        float4 z = make_float4(0.f, 0.f, 0.f, 0.f);
        if (col >= r && col < r + 4) ((float*)&z)[col - r] = 1.0f;
        *(float4*)&myc[r] = z;
    }

    for (int B = 0; B < 511; B += 64) {
        const int Bend = (B + 64 < 511) ? B + 64 : 511;
        const int LB = 511 - B;
        const int LC = ((LB + 127) >> 7) << 4;       // {64,64,48,48,32,32,16,16}
        __syncthreads();                             // rows reshuffle + myc handoff
        switch (LC) {
            case 64: do_block<64>(B, Bend, w, lane, myc, ring0, Csh, Dsh, A0sh, slotf4); break;
            case 48: do_block<48>(B, Bend, w, lane, myc, ring0, Csh, Dsh, A0sh, slotf4); break;
            case 32: do_block<32>(B, Bend, w, lane, myc, ring0, Csh, Dsh, A0sh, slotf4); break;
            default: do_block<16>(B, Bend, w, lane, myc, ring0, Csh, Dsh, A0sh, slotf4); break;
        }
    }
    __syncthreads();

    // writeback: warp w rows [w*64, w*64+64), coalesced across lanes
    if (mat == 0) {
        for (int r = w * 64; r < w * 64 + 64; r++)
            g_U[r * NN + col] = __ldg(&dU[r]) * myc[r];
    } else {
        for (int r = w * 64; r < w * 64 + 64; r++)
            g_Vs[r * NN + col] = __ldg(&sigma[r]) * __ldg(&dV[r]) * myc[r];
    }
}

// ---------------- 3) W = U @ (sigma*delta_V * V), bf16 hi/lo output ----------------
__global__ void wgemm_kernel() {
    __shared__ float As[32][33];
    __shared__ float Bs[32][33];
    const int tx = threadIdx.x, ty = threadIdx.y;
    const int a = blockIdx.y * 32 + ty;
    const int b = blockIdx.x * 32 + tx;
    float acc = 0.0f;
    for (int kt = 0; kt < NN; kt += 32) {
        As[ty][tx] = g_U [a * NN + kt + tx];
        Bs[ty][tx] = g_Vs[(kt + ty) * NN + b];
        __syncthreads();
        #pragma unroll
        for (int kk = 0; kk < 32; kk++)
            acc += As[ty][kk] * Bs[kk][tx];
        __syncthreads();
    }
    __nv_bfloat16 hi = __float2bfloat16_rn(acc);
    g_whi[a * NN + b] = hi;
    g_wlo[a * NN + b] = __float2bfloat16_rn(acc - __bfloat162float(hi));
}

// ---------------- 4) out = x @ W^T, 3-term bf16 wmma, cp.async pipeline ----------------
#define GBK 32
#define XLD 40
#define TILE_H (128 * XLD)
#define STAGE_H (4 * TILE_H)

__global__ void __launch_bounds__(256, 2) bfgemm_kernel(float* __restrict__ C) {
    __shared__ __nv_bfloat16 sbuf[2 * STAGE_H];

    const int tid  = threadIdx.x;
    const int warp = tid >> 5;
    const int m0 = blockIdx.y * 128;
    const int n0 = blockIdx.x * 128;
    const int wm = (warp >> 2) * 64;
    const int wn = (warp & 3) * 32;

    wmma::fragment<wmma::accumulator, 16, 16, 16, float> acc[4][2];
    #pragma unroll
    for (int i = 0; i < 4; i++)
        #pragma unroll
        for (int j = 0; j < 2; j++) wmma::fill_fragment(acc[i][j], 0.0f);

    const int lr = tid >> 1;
    const int lh = (tid & 1) * 16;
    const __nv_bfloat16* gx[4];
    gx[0] = g_xhi + (size_t)(m0 + lr) * NN + lh;
    gx[1] = g_xlo + (size_t)(m0 + lr) * NN + lh;
    gx[2] = g_whi + (size_t)(n0 + lr) * NN + lh;
    gx[3] = g_wlo + (size_t)(n0 + lr) * NN + lh;
    const uint32_t sb0 = smem_u32(sbuf);
    const uint32_t dst_row = (uint32_t)(lr * XLD + lh) * 2;

    #define COPY_TILE(t, stg) do { \
        uint32_t _b = sb0 + (stg) * (STAGE_H * 2); \
        int _k = (t) * GBK; \
        _Pragma("unroll") \
        for (int _p = 0; _p < 4; _p++) { \
            uint32_t _d = _b + _p * (TILE_H * 2) + dst_row; \
            CP_ASYNC16(_d,      gx[_p] + _k); \
            CP_ASYNC16(_d + 16, gx[_p] + _k + 8); \
        } } while (0)

    COPY_TILE(0, 0);
    CP_COMMIT();

    for (int t = 0; t < NN / GBK; t++) {
        const int cur = t & 1;
        if (t + 1 < NN / GBK) { COPY_TILE(t + 1, cur ^ 1); CP_COMMIT(); CP_WAIT(1); }
        else                  { CP_WAIT(0); }
        __syncthreads();

        const __nv_bfloat16* xh = sbuf + cur * STAGE_H;
        const __nv_bfloat16* xl = xh + TILE_H;
        const __nv_bfloat16* wh = xl + TILE_H;
        const __nv_bfloat16* wl = wh + TILE_H;

        #pragma unroll
        for (int ks = 0; ks < GBK; ks += 16) {
            wmma::fragment<wmma::matrix_a, 16, 16, 16, __nv_bfloat16, wmma::row_major> ah[4], al[4];
            wmma::fragment<wmma::matrix_b, 16, 16, 16, __nv_bfloat16, wmma::col_major> bh[2], bl[2];
            #pragma unroll
            for (int i = 0; i < 4; i++) {
                wmma::load_matrix_sync(ah[i], xh + (wm + i * 16) * XLD + ks, XLD);
                wmma::load_matrix_sync(al[i], xl + (wm + i * 16) * XLD + ks, XLD);
            }
            #pragma unroll
            for (int j = 0; j < 2; j++) {
                wmma::load_matrix_sync(bh[j], wh + (wn + j * 16) * XLD + ks, XLD);
                wmma::load_matrix_sync(bl[j], wl + (wn + j * 16) * XLD + ks, XLD);
            }
            #pragma unroll
            for (int i = 0; i < 4; i++)
                #pragma unroll
                for (int j = 0; j < 2; j++) {
                    wmma::mma_sync(acc[i][j], ah[i], bh[j], acc[i][j]);
                    wmma::mma_sync(acc[i][j], ah[i], bl[j], acc[i][j]);
                    wmma::mma_sync(acc[i][j], al[i], bh[j], acc[i][j]);
                }
        }
        __syncthreads();
    }

    #pragma unroll
    for (int i = 0; i < 4; i++)
        #pragma unroll
        for (int j = 0; j < 2; j++)
            wmma::store_matrix_sync(&C[(size_t)(m0 + wm + i * 16) * NN + n0 + wn + j * 16],
                                    acc[i][j], NN, wmma::mem_row_major);
}

// ---------------- launch ----------------
extern "C" void kernel_launch(void* const* d_in, const int* in_sizes, int n_in,
                              void* d_out, int out_size) {
    const float* x     = (const float*)d_in[0];
    const float* phiU  = (const float*)d_in[1];
    const float* dU    = (const float*)d_in[2];
    const float* phiV  = (const float*)d_in[3];
    const float* dV    = (const float*)d_in[4];
    const float* sigma = (const float*)d_in[5];
    float* out = (float*)d_out;

    const int recon_smem = 32 * RST * 4 + 1024 * 8 + (16 + 512 + 64) * 4;
    cudaFuncSetAttribute(reconstruct_kernel,
                         cudaFuncAttributeMaxDynamicSharedMemorySize, recon_smem);

    setup_cs_kernel<<<(2 * 512 * 512 + 255) / 256, 256>>>(phiU, phiV);
    xsplit_kernel<<<32768 * 512 / (256 * 8), 256>>>(x);
    reconstruct_kernel<<<32, 256, recon_smem>>>(dU, dV, sigma);
    wgemm_kernel<<<dim3(16, 16), dim3(32, 32)>>>();
    bfgemm_kernel<<<dim3(NN / 128, 32768 / 128), 256>>>(out);
}

// round 13
// speedup vs baseline: 1.6950x; 1.2339x over previous
#include <cuda_runtime.h>
#include <cuda_fp16.h>
#include <mma.h>
#include <cstdint>
using namespace nvcuda;

#define NN 512
#define RST 516

// ---------------- device scratch (no allocations allowed) ----------------
__device__ __align__(16) float2 g_slot[2 * 512 * 512];   // 4 MB
__device__ float g_U [NN * NN];
__device__ float g_Vs[NN * NN];
__device__ __align__(16) __half g_xh[32768 * 512];       // 32 MB (fp16 x)
__device__ __align__(16) __half g_wh[NN * NN];
__device__ __align__(16) __half g_wl[NN * NN];

__device__ __forceinline__ uint32_t smem_u32(const void* p) {
    uint32_t a;
    asm("{ .reg .u64 t; cvta.to.shared.u64 t, %1; cvt.u32.u64 %0, t; }" : "=r"(a) : "l"(p));
    return a;
}
#define CP_ASYNC16(sa, gp) \
    asm volatile("cp.async.ca.shared.global [%0], [%1], 16;" :: "r"(sa), "l"(gp) : "memory")
#define CP_COMMIT() asm volatile("cp.async.commit_group;" ::: "memory")
#define CP_WAIT(n)  asm volatile("cp.async.wait_group %0;" :: "n"(n) : "memory")

// ---------------- 1) cos/sin precompute into padded slots ----------------
__global__ void setup_cs_kernel(const float* __restrict__ phiU,
                                const float* __restrict__ phiV) {
    int tid = blockIdx.x * blockDim.x + threadIdx.x;
    if (tid >= 2 * 512 * 512) return;
    int mat = tid >> 18;
    int r   = tid & 262143;
    int i   = r >> 9;
    int m   = r & 511;
    float c = 1.0f, s = 0.0f;
    if (m < 511 - i) {
        int k = i * 511 - (i * (i - 1)) / 2 + m;
        float ph = mat ? __ldg(&phiV[k]) : __ldg(&phiU[k]);
        sincosf(ph, &s, &c);
    }
    g_slot[tid] = make_float2(c, s);
}

// ---------------- 1b) x -> fp16 (one pass) ----------------
__global__ void xsplit_kernel(const float* __restrict__ x) {
    int i = (blockIdx.x * 256 + threadIdx.x) * 8;
    float4 v0 = *(const float4*)(x + i);
    float4 v1 = *(const float4*)(x + i + 4);
    __half h[8];
    #pragma unroll
    for (int e = 0; e < 8; e++) {
        float f = (e < 4) ? ((const float*)&v0)[e] : ((const float*)&v1)[e - 4];
        h[e] = __float2half_rn(f);
    }
    *(uint4*)(g_xh + i) = *(uint4*)h;
}

// ---------------- 2) Givens-mesh reconstruction ----------------
// W=8 warps; lane owns a column. Per 64-pivot block, warp w owns the FIXED
// rotation range m in [w*LC, (w+1)*LC); rows j=511-m live in REGISTERS.
// Steps with m >= L use the slot padding (c=1,s=0) = exact identity.
// Phase1/phase2 chains split 2-way. One __syncthreads per pivot.
template<int LC>
__device__ __forceinline__ void do_block(
    int B, int Bend, int w, int lane,
    float* __restrict__ myc, float2* __restrict__ ring0,
    float* __restrict__ Csh, float* __restrict__ Dsh, float* __restrict__ A0sh,
    const float4* __restrict__ slotf4)
{
    const int m0  = w * LC;
    const int f40 = m0 >> 1;
    const bool lact = lane < (LC / 2);
    const int fidx = f40 + lane;

    float v[LC];
    #pragma unroll
    for (int k = 0; k < LC; k++) v[k] = myc[511 - m0 - k];

    float4 pf, pf2;
    {
        float4* rw = (float4*)(ring0 + (B & 1) * 512);
        if (lact) {
            rw[fidx] = __ldg(slotf4 + B * 256 + fidx);
            int i1 = (B + 1 <= 510) ? B + 1 : 510;
            int i2 = (B + 2 <= 510) ? B + 2 : 510;
            pf  = __ldg(slotf4 + i1 * 256 + fidx);
            pf2 = __ldg(slotf4 + i2 * 256 + fidx);
        }
        __syncwarp();
    }

    for (int i = B; i < Bend; i++) {
        const int par = i & 1;
        const int L = 511 - i;
        const float4* rf = (const float4*)(ring0 + par * 512) + f40;

        if (i == B && w == 7) A0sh[par * 32 + lane] = myc[B];

        // ---- phase 1: two half-chains ----
        float C0 = 1.f, D0 = 0.f, C1 = 1.f, D1 = 0.f;
        #pragma unroll
        for (int q = 0; q < LC / 4; q++) {
            float4 r = rf[q];
            D0 = fmaf(r.x, D0, r.y * v[2 * q]);     C0 *= r.x;
            D0 = fmaf(r.z, D0, r.w * v[2 * q + 1]); C0 *= r.z;
        }
        #pragma unroll
        for (int q = LC / 4; q < LC / 2; q++) {
            float4 r = rf[q];
            D1 = fmaf(r.x, D1, r.y * v[2 * q]);     C1 *= r.x;
            D1 = fmaf(r.z, D1, r.w * v[2 * q + 1]); C1 *= r.z;
        }
        const float Cw = C0 * C1;
        const float Dw = fmaf(C1, D0, D1);

        if (lane == 0) Csh[par * 8 + w] = Cw;
        Dsh[par * 256 + w * 32 + lane] = Dw;

        if (i + 1 < Bend) {
            __syncwarp();
            float4* rw = (float4*)(ring0 + (par ^ 1) * 512);
            if (lact) {
                rw[fidx] = pf;
                pf = pf2;
                int nx = (i + 3 <= 510) ? i + 3 : 510;
                pf2 = __ldg(slotf4 + nx * 256 + fidx);
            }
        }

        __syncthreads();                           // the one barrier: stitch

        float A = A0sh[par * 32 + lane];
        #pragma unroll 7
        for (int kk = 0; kk < w; kk++)
            A = fmaf(Csh[par * 8 + kk], A, -Dsh[par * 256 + kk * 32 + lane]);
        if (w == 7) myc[i] = fmaf(Cw, A, -Dw);

        // ---- phase 2: two half-chains; 2nd seeds from A1 = C0*A - D0 ----
        float A1 = fmaf(C0, A, -D0);
        #pragma unroll
        for (int q = 0; q < LC / 4; q++) {
            float4 r = rf[q];
            { float u = v[2 * q];     float t1 = r.y * u;
              v[2 * q]     = fmaf(r.y, A, r.x * u); A = fmaf(r.x, A, -t1); }
            { float u = v[2 * q + 1]; float t1 = r.w * u;
              v[2 * q + 1] = fmaf(r.w, A, r.z * u); A = fmaf(r.z, A, -t1); }
        }
        #pragma unroll
        for (int q = LC / 4; q < LC / 2; q++) {
            float4 r = rf[q];
            { float u = v[2 * q];     float t1 = r.y * u;
              v[2 * q]     = fmaf(r.y, A1, r.x * u); A1 = fmaf(r.x, A1, -t1); }
            { float u = v[2 * q + 1]; float t1 = r.w * u;
              v[2 * q + 1] = fmaf(r.w, A1, r.z * u); A1 = fmaf(r.z, A1, -t1); }
        }

        if (i + 1 < Bend) {
            int idx = (L - 1) - m0;
            if (idx >= 0 && idx < LC) {
                float val = 0.f;
                #pragma unroll
                for (int k = 0; k < LC; k++) if (k == idx) val = v[k];
                A0sh[((i + 1) & 1) * 32 + lane] = val;
            }
        }
    }

    #pragma unroll
    for (int k = 0; k < LC; k++)
        if (m0 + k <= 511 - Bend) myc[511 - m0 - k] = v[k];
}

__global__ void __launch_bounds__(256) reconstruct_kernel(const float* __restrict__ dU,
                                                          const float* __restrict__ dV,
                                                          const float* __restrict__ sigma) {
    extern __shared__ float sm[];
    float*  cols  = sm;
    float2* ring0 = (float2*)(sm + 32 * RST);
    float*  Csh   = (float*)(ring0 + 1024);
    float*  Dsh   = Csh + 16;
    float*  A0sh  = Dsh + 512;

    const int mat     = blockIdx.x >> 4;
    const int colbase = (blockIdx.x & 15) << 5;
    const int tid  = threadIdx.x;
    const int w    = tid >> 5;
    const int lane = tid & 31;
    const int col  = colbase + lane;

    const float4* slotf4 = (const float4*)(g_slot + mat * 262144);
    float* myc = cols + lane * RST;

    for (int r = w * 64; r < w * 64 + 64; r += 4) {
        float4 z = make_float4(0.f, 0.f, 0.f, 0.f);
        if (col >= r && col < r + 4) ((float*)&z)[col - r] = 1.0f;
        *(float4*)&myc[r] = z;
    }

    for (int B = 0; B < 511; B += 64) {
        const int Bend = (B + 64 < 511) ? B + 64 : 511;
        const int LB = 511 - B;
        const int LC = ((LB + 63) >> 6) << 3;   // {64,56,48,40,32,24,16,8}
        __syncthreads();
        switch (LC) {
            case 64: do_block<64>(B, Bend, w, lane, myc, ring0, Csh, Dsh, A0sh, slotf4); break;
            case 56: do_block<56>(B, Bend, w, lane, myc, ring0, Csh, Dsh, A0sh, slotf4); break;
            case 48: do_block<48>(B, Bend, w, lane, myc, ring0, Csh, Dsh, A0sh, slotf4); break;
            case 40: do_block<40>(B, Bend, w, lane, myc, ring0, Csh, Dsh, A0sh, slotf4); break;
            case 32: do_block<32>(B, Bend, w, lane, myc, ring0, Csh, Dsh, A0sh, slotf4); break;
            case 24: do_block<24>(B, Bend, w, lane, myc, ring0, Csh, Dsh, A0sh, slotf4); break;
            case 16: do_block<16>(B, Bend, w, lane, myc, ring0, Csh, Dsh, A0sh, slotf4); break;
            default: do_block< 8>(B, Bend, w, lane, myc, ring0, Csh, Dsh, A0sh, slotf4); break;
        }
    }
    __syncthreads();

    if (mat == 0) {
        for (int r = w * 64; r < w * 64 + 64; r++)
            g_U[r * NN + col] = __ldg(&dU[r]) * myc[r];
    } else {
        for (int r = w * 64; r < w * 64 + 64; r++)
            g_Vs[r * NN + col] = __ldg(&sigma[r]) * __ldg(&dV[r]) * myc[r];
    }
}

// ---------------- 3) W = U @ (sigma*delta_V * V), fp16 hi/lo output ----------------
__global__ void wgemm_kernel() {
    __shared__ float As[32][33];
    __shared__ float Bs[32][33];
    const int tx = threadIdx.x, ty = threadIdx.y;
    const int a = blockIdx.y * 32 + ty;
    const int b = blockIdx.x * 32 + tx;
    float acc = 0.0f;
    for (int kt = 0; kt < NN; kt += 32) {
        As[ty][tx] = g_U [a * NN + kt + tx];
        Bs[ty][tx] = g_Vs[(kt + ty) * NN + b];
        __syncthreads();
        #pragma unroll
        for (int kk = 0; kk < 32; kk++)
            acc += As[ty][kk] * Bs[kk][tx];
        __syncthreads();
    }
    __half hi = __float2half_rn(acc);
    g_wh[a * NN + b] = hi;
    g_wl[a * NN + b] = __float2half_rn(acc - __half2float(hi));
}

// ---------------- 4) out = x @ W^T, 2-term fp16 wmma, cp.async pipeline ----------------
// out = xh * (wh + wl); xh = fp16(x), W = wh + wl (fp16 split).
#define GBK 32
#define XLD 40
#define TILE_H (128 * XLD)
#define STAGE_H (3 * TILE_H)     // xh, wh, wl

__global__ void __launch_bounds__(256, 2) hgemm_kernel(float* __restrict__ C) {
    __shared__ __half sbuf[2 * STAGE_H];

    const int tid  = threadIdx.x;
    const int warp = tid >> 5;
    const int m0 = blockIdx.y * 128;
    const int n0 = blockIdx.x * 128;
    const int wm = (warp >> 2) * 64;
    const int wn = (warp & 3) * 32;

    wmma::fragment<wmma::accumulator, 16, 16, 16, float> acc[4][2];
    #pragma unroll
    for (int i = 0; i < 4; i++)
        #pragma unroll
        for (int j = 0; j < 2; j++) wmma::fill_fragment(acc[i][j], 0.0f);

    const int lr = tid >> 1;
    const int lh = (tid & 1) * 16;
    const __half* gx[3];
    gx[0] = g_xh + (size_t)(m0 + lr) * NN + lh;
    gx[1] = g_wh + (size_t)(n0 + lr) * NN + lh;
    gx[2] = g_wl + (size_t)(n0 + lr) * NN + lh;
    const uint32_t sb0 = smem_u32(sbuf);
    const uint32_t dst_row = (uint32_t)(lr * XLD + lh) * 2;

    #define COPY_TILE(t, stg) do { \
        uint32_t _b = sb0 + (stg) * (STAGE_H * 2); \
        int _k = (t) * GBK; \
        _Pragma("unroll") \
        for (int _p = 0; _p < 3; _p++) { \
            uint32_t _d = _b + _p * (TILE_H * 2) + dst_row; \
            CP_ASYNC16(_d,      gx[_p] + _k); \
            CP_ASYNC16(_d + 16, gx[_p] + _k + 8); \
        } } while (0)

    COPY_TILE(0, 0);
    CP_COMMIT();

    for (int t = 0; t < NN / GBK; t++) {
        const int cur = t & 1;
        if (t + 1 < NN / GBK) { COPY_TILE(t + 1, cur ^ 1); CP_COMMIT(); CP_WAIT(1); }
        else                  { CP_WAIT(0); }
        __syncthreads();

        const __half* xh = sbuf + cur * STAGE_H;
        const __half* wh = xh + TILE_H;
        const __half* wl = wh + TILE_H;

        #pragma unroll
        for (int ks = 0; ks < GBK; ks += 16) {
            wmma::fragment<wmma::matrix_a, 16, 16, 16, __half, wmma::row_major> ah[4];
            wmma::fragment<wmma::matrix_b, 16, 16, 16, __half, wmma::col_major> bh[2], bl[2];
            #pragma unroll
            for (int i = 0; i < 4; i++)
                wmma::load_matrix_sync(ah[i], xh + (wm + i * 16) * XLD + ks, XLD);
            #pragma unroll
            for (int j = 0; j < 2; j++) {
                wmma::load_matrix_sync(bh[j], wh + (wn + j * 16) * XLD + ks, XLD);
                wmma::load_matrix_sync(bl[j], wl + (wn + j * 16) * XLD + ks, XLD);
            }
            #pragma unroll
            for (int i = 0; i < 4; i++)
                #pragma unroll
                for (int j = 0; j < 2; j++) {
                    wmma::mma_sync(acc[i][j], ah[i], bh[j], acc[i][j]);
                    wmma::mma_sync(acc[i][j], ah[i], bl[j], acc[i][j]);
                }
        }
        __syncthreads();
    }

    #pragma unroll
    for (int i = 0; i < 4; i++)
        #pragma unroll
        for (int j = 0; j < 2; j++)
            wmma::store_matrix_sync(&C[(size_t)(m0 + wm + i * 16) * NN + n0 + wn + j * 16],
                                    acc[i][j], NN, wmma::mem_row_major);
}

// ---------------- launch ----------------
extern "C" void kernel_launch(void* const* d_in, const int* in_sizes, int n_in,
                              void* d_out, int out_size) {
    const float* x     = (const float*)d_in[0];
    const float* phiU  = (const float*)d_in[1];
    const float* dU    = (const float*)d_in[2];
    const float* phiV  = (const float*)d_in[3];
    const float* dV    = (const float*)d_in[4];
    const float* sigma = (const float*)d_in[5];
    float* out = (float*)d_out;

    const int recon_smem = 32 * RST * 4 + 1024 * 8 + (16 + 512 + 64) * 4;
    cudaFuncSetAttribute(reconstruct_kernel,
                         cudaFuncAttributeMaxDynamicSharedMemorySize, recon_smem);

    setup_cs_kernel<<<(2 * 512 * 512 + 255) / 256, 256>>>(phiU, phiV);
    xsplit_kernel<<<32768 * 512 / (256 * 8), 256>>>(x);
    reconstruct_kernel<<<32, 256, recon_smem>>>(dU, dV, sigma);
    wgemm_kernel<<<dim3(16, 16), dim3(32, 32)>>>();
    hgemm_kernel<<<dim3(NN / 128, 32768 / 128), 256>>>(out);
}